// round 5
// baseline (speedup 1.0000x reference)
#include <cuda_runtime.h>
#include <cuda_bf16.h>

namespace {

constexpr int Bb = 64, Cc = 3, Hh = 384, Ww = 384, Pp = 16, Ee = 768;
constexpr int NP = (Hh / Pp) * (Ww / Pp);   // 576 patches per image
constexpr int Mm = Bb * NP;                 // 36864 total patches (GEMM M)
constexpr int Kk = Cc * Pp * Pp;            // 768 (GEMM K)

constexpr int BM = 128, BN = 128, BK = 16;
constexpr int TM = 8, TN = 8;

// Fused gather + SGEMM:
//   tokens[m][e] = sum_k patch[m][k] * w[e][k] + bias[e]
// where patch[m][k] with k = c*256 + r*16 + q is x[b, c, ys[m]+r, xs[m]+q].
// With BK=16 and K-tiles aligned to 16, one A K-tile row is a CONTIGUOUS
// 16-float span of x: x[b, c, ys[m]+r, xs[m] .. xs[m]+15]. So the gather is
// just a coalesced row load fused into the GEMM tile load.
__global__ __launch_bounds__(256, 2)
void patch_embed_gemm(const float* __restrict__ x,
                      const int*   __restrict__ ys,
                      const int*   __restrict__ xs,
                      const float* __restrict__ w,
                      const float* __restrict__ bias,
                      float*       __restrict__ out)
{
    __shared__ float As[BK][BM];
    __shared__ float Bs[BK][BN];

    const int tid = threadIdx.x;
    const int m0 = blockIdx.y * BM;
    const int n0 = blockIdx.x * BN;

    // Loader mapping: 256 threads cover 128 rows x 2 halves of 8 floats.
    const int row  = tid >> 1;      // 0..127
    const int half = tid & 1;       // 0/1
    const int kh   = half * 8;      // 0 or 8

    const int mload = m0 + row;
    const int bimg  = mload / NP;
    const int y0    = ys[mload];
    const int x0    = xs[mload];
    const float* wsrc_base = w + (size_t)(n0 + row) * Kk + kh;
    const float* xbase = x + ((size_t)bimg * Cc * Hh + y0) * Ww + x0 + kh;

    // Compute mapping: 16x16 thread grid, each 8x8 outputs.
    const int tnq   = tid & 15;
    const int tmq   = tid >> 4;
    const int aBase = tmq * TM;
    const int bBase = tnq * TN;

    float acc[TM][TN];
    #pragma unroll
    for (int i = 0; i < TM; ++i)
        #pragma unroll
        for (int j = 0; j < TN; ++j) acc[i][j] = 0.f;

    #pragma unroll 1
    for (int kt = 0; kt < Kk / BK; ++kt) {
        const int kbase = kt * BK;
        const int c = kbase >> 8;          // channel
        const int r = (kbase & 255) >> 4;  // row within patch
        const float* asrc = xbase + ((size_t)c * Hh + r) * Ww;
        #pragma unroll
        for (int j = 0; j < 8; ++j) As[kh + j][row] = asrc[j];

        const float* wsrc = wsrc_base + kbase;
        #pragma unroll
        for (int j = 0; j < 8; ++j) Bs[kh + j][row] = wsrc[j];

        __syncthreads();

        #pragma unroll
        for (int k = 0; k < BK; ++k) {
            float a[TM], bv[TN];
            #pragma unroll
            for (int i = 0; i < TM; i += 4)
                *(float4*)&a[i] = *(const float4*)&As[k][aBase + i];
            #pragma unroll
            for (int j = 0; j < TN; j += 4)
                *(float4*)&bv[j] = *(const float4*)&Bs[k][bBase + j];
            #pragma unroll
            for (int i = 0; i < TM; ++i)
                #pragma unroll
                for (int j = 0; j < TN; ++j)
                    acc[i][j] = fmaf(a[i], bv[j], acc[i][j]);
        }
        __syncthreads();
    }

    // Epilogue: add bias, store.
    float bv[TN];
    #pragma unroll
    for (int j = 0; j < TN; ++j) bv[j] = bias[n0 + bBase + j];

    #pragma unroll
    for (int i = 0; i < TM; ++i) {
        const int m = m0 + aBase + i;
        float* orow = out + (size_t)m * Ee + n0 + bBase;
        #pragma unroll
        for (int j = 0; j < TN; j += 4) {
            float4 v;
            v.x = acc[i][j + 0] + bv[j + 0];
            v.y = acc[i][j + 1] + bv[j + 1];
            v.z = acc[i][j + 2] + bv[j + 2];
            v.w = acc[i][j + 3] + bv[j + 3];
            *(float4*)&orow[j] = v;
        }
    }
}

// patch_positions = stack([ys, xs], -1) -> [B, N, 2]. The harness's output
// buffer uses a single dtype (float32), so the int coordinates must be
// written as float VALUES (exact for 0..368), not bitcast ints.
__global__ void write_positions(const int* __restrict__ ys,
                                const int* __restrict__ xs,
                                float* __restrict__ pos)
{
    int i = blockIdx.x * blockDim.x + threadIdx.x;
    if (i < Mm) {
        pos[2 * i + 0] = (float)ys[i];
        pos[2 * i + 1] = (float)xs[i];
    }
}

} // namespace

extern "C" void kernel_launch(void* const* d_in, const int* in_sizes, int n_in,
                              void* d_out, int out_size) {
    const float* x    = (const float*)d_in[0];
    const int*   ys   = (const int*)d_in[1];
    const int*   xs   = (const int*)d_in[2];
    const float* w    = (const float*)d_in[3];
    const float* bias = (const float*)d_in[4];
    float* out = (float*)d_out;

    dim3 grid(Ee / BN, Mm / BM);   // 6 x 288 = 1728 CTAs
    patch_embed_gemm<<<grid, 256>>>(x, ys, xs, w, bias, out);

    // Positions live immediately after the tokens (tokens region is exactly
    // 256B-aligned, so no padding ambiguity).
    float* pos = out + (size_t)Mm * Ee;
    write_positions<<<(Mm + 255) / 256, 256>>>(ys, xs, pos);
}

// round 7
// speedup vs baseline: 2.1417x; 2.1417x over previous
#include <cuda_runtime.h>
#include <cuda_bf16.h>
#include <cstdint>

namespace {

constexpr int Bb = 64, Cc = 3, Hh = 384, Ww = 384, Pp = 16, Ee = 768;
constexpr int NP = (Hh / Pp) * (Ww / Pp);   // 576
constexpr int Mm = Bb * NP;                 // 36864
constexpr int Kk = Cc * Pp * Pp;            // 768

constexpr int BM = 128, BN = 128, BK = 32;  // CTA tile
constexpr int THREADS = 512;                // 16 warps: 4 (M) x 4 (N), 32x32 each
constexpr int SA = BK + 8;                  // smem row stride (bf16 elems) -> 80B, LDSM conflict-free
constexpr int NITER = Kk / BK;              // 24

__device__ __forceinline__ uint32_t smem_u32(const void* p) {
    uint32_t a;
    asm("{ .reg .u64 t; cvta.to.shared.u64 t, %1; cvt.u32.u64 %0, t; }" : "=r"(a) : "l"(p));
    return a;
}

__device__ __forceinline__ void ldsm_x4(uint32_t addr, uint32_t& r0, uint32_t& r1,
                                        uint32_t& r2, uint32_t& r3) {
    asm volatile("ldmatrix.sync.aligned.m8n8.x4.shared.b16 {%0,%1,%2,%3}, [%4];"
                 : "=r"(r0), "=r"(r1), "=r"(r2), "=r"(r3) : "r"(addr));
}

__device__ __forceinline__ void mma_bf16(float* d, const uint32_t* a, const uint32_t* b) {
    asm volatile(
        "mma.sync.aligned.m16n8k16.row.col.f32.bf16.bf16.f32 "
        "{%0,%1,%2,%3}, {%4,%5,%6,%7}, {%8,%9}, {%0,%1,%2,%3};"
        : "+f"(d[0]), "+f"(d[1]), "+f"(d[2]), "+f"(d[3])
        : "r"(a[0]), "r"(a[1]), "r"(a[2]), "r"(a[3]), "r"(b[0]), "r"(b[1]));
}

// fp32 -> bf16 hi + bf16 lo residual; hi*hi + hi*lo + lo*hi recovers ~16
// mantissa bits (lo*lo ~2^-18 relative, dropped).
__device__ __forceinline__ void split2(float v0, float v1, uint32_t& hi, uint32_t& lo) {
    __nv_bfloat16 h0 = __float2bfloat16(v0);
    __nv_bfloat16 h1 = __float2bfloat16(v1);
    __nv_bfloat16 l0 = __float2bfloat16(v0 - __bfloat162float(h0));
    __nv_bfloat16 l1 = __float2bfloat16(v1 - __bfloat162float(h1));
    hi = (uint32_t)__bfloat16_as_ushort(h0) | ((uint32_t)__bfloat16_as_ushort(h1) << 16);
    lo = (uint32_t)__bfloat16_as_ushort(l0) | ((uint32_t)__bfloat16_as_ushort(l1) << 16);
}

// Fused gather + split-bf16 HMMA GEMM:
//   tokens[m][e] = sum_k patch[m][k] * w[e][k] + bias[e]
// A K-rows are contiguous 16-float image spans (k = c*256 + r*16 + q), so the
// off-grid gather fuses into the tile load. mma.sync m16n8k16 row.col matches
// our layouts directly: A rows K-major, B (= w rows) K-major.
__global__ __launch_bounds__(THREADS, 1)
void patch_embed_hmma(const float* __restrict__ x,
                      const int*   __restrict__ ys,
                      const int*   __restrict__ xs,
                      const float* __restrict__ w,
                      const float* __restrict__ bias,
                      float*       __restrict__ out)
{
    __shared__ __nv_bfloat16 AsH[BM * SA], AsL[BM * SA];
    __shared__ __nv_bfloat16 BsH[BN * SA], BsL[BN * SA];

    const int tid = threadIdx.x;
    const int warpid = tid >> 5, lane = tid & 31;
    const int wm = warpid & 3, wn = warpid >> 2;     // warp coords in 4x4 grid
    const int m0 = blockIdx.y * BM, n0 = blockIdx.x * BN;

    // ---- loader mapping: 4 threads per row, 8 floats each ----
    const int lrow = tid >> 2;          // 0..127
    const int lseg = tid & 3;           // which 8-float chunk of the 32-K slice
    const int am = m0 + lrow;
    const int bimg = am / NP;
    const float* arow = x + ((size_t)(bimg * Cc) * Hh + ys[am]) * (size_t)Ww + xs[am];
    const float* brow = w + (size_t)(n0 + lrow) * Kk + lseg * 8;

    float af[8], bf[8];
    {   // prefetch kt = 0
        const int k0 = lseg * 8;
        const int c = k0 >> 8, r = (k0 >> 4) & 15, q = k0 & 15;
        const float* src = arow + ((size_t)c * Hh + r) * Ww + q;
        #pragma unroll
        for (int j = 0; j < 8; ++j) af[j] = __ldg(src + j);
        float4 v0 = __ldg((const float4*)brow), v1 = __ldg((const float4*)brow + 1);
        bf[0]=v0.x; bf[1]=v0.y; bf[2]=v0.z; bf[3]=v0.w;
        bf[4]=v1.x; bf[5]=v1.y; bf[6]=v1.z; bf[7]=v1.w;
    }

    float acc[2][4][4];
    #pragma unroll
    for (int i = 0; i < 2; ++i)
        #pragma unroll
        for (int j = 0; j < 4; ++j)
            #pragma unroll
            for (int v = 0; v < 4; ++v) acc[i][j][v] = 0.f;

    // ldmatrix lane addressing (elements):
    //   A x4: g=lane/8, idx=lane%8 -> row m0w+(g%2)*8+idx, col k0+(g/2)*8
    //   B x4: g=lane/8, idx=lane%8 -> row n0w+(g/2)*8+idx, col k0+(g%2)*8
    const int g = lane >> 3, gi = lane & 7;
    const uint32_t aBase = smem_u32(AsH);          // AsL at fixed offset
    const uint32_t bBase = smem_u32(BsH);
    const uint32_t aLoff = (uint32_t)((char*)AsL - (char*)AsH);
    const uint32_t bLoff = (uint32_t)((char*)BsL - (char*)BsH);
    const int aRow = wm * 32 + (g & 1) * 8 + gi;   // + mt*16
    const int aCol = (g >> 1) * 8;                 // + ks*16
    const int bRow = wn * 32 + (g >> 1) * 8 + gi;  // + np*16
    const int bCol = (g & 1) * 8;                  // + ks*16

    const int sts = lrow * SA + lseg * 8;

    #pragma unroll 1
    for (int kt = 0; kt < NITER; ++kt) {
        // split + store to smem
        uint32_t hi[4], lo[4];
        #pragma unroll
        for (int j = 0; j < 4; ++j) split2(af[2*j], af[2*j+1], hi[j], lo[j]);
        *(uint4*)&AsH[sts] = make_uint4(hi[0], hi[1], hi[2], hi[3]);
        *(uint4*)&AsL[sts] = make_uint4(lo[0], lo[1], lo[2], lo[3]);
        #pragma unroll
        for (int j = 0; j < 4; ++j) split2(bf[2*j], bf[2*j+1], hi[j], lo[j]);
        *(uint4*)&BsH[sts] = make_uint4(hi[0], hi[1], hi[2], hi[3]);
        *(uint4*)&BsL[sts] = make_uint4(lo[0], lo[1], lo[2], lo[3]);
        __syncthreads();

        // prefetch next k-slice (LDG latency hidden under the mma phase)
        if (kt + 1 < NITER) {
            const int k0 = (kt + 1) * BK + lseg * 8;
            const int c = k0 >> 8, r = (k0 >> 4) & 15, q = k0 & 15;
            const float* src = arow + ((size_t)c * Hh + r) * Ww + q;
            #pragma unroll
            for (int j = 0; j < 8; ++j) af[j] = __ldg(src + j);
            const float4* bsrc = (const float4*)(brow + (kt + 1) * BK);
            float4 v0 = __ldg(bsrc), v1 = __ldg(bsrc + 1);
            bf[0]=v0.x; bf[1]=v0.y; bf[2]=v0.z; bf[3]=v0.w;
            bf[4]=v1.x; bf[5]=v1.y; bf[6]=v1.z; bf[7]=v1.w;
        }

        #pragma unroll
        for (int ks = 0; ks < 2; ++ks) {
            const int kk = ks * 16;
            uint32_t aH[2][4], aL[2][4], bH[4][2], bL[4][2];
            #pragma unroll
            for (int mt = 0; mt < 2; ++mt) {
                uint32_t off = (uint32_t)(((aRow + mt * 16) * SA + aCol + kk) * 2);
                ldsm_x4(aBase + off, aH[mt][0], aH[mt][1], aH[mt][2], aH[mt][3]);
                ldsm_x4(aBase + aLoff + off, aL[mt][0], aL[mt][1], aL[mt][2], aL[mt][3]);
            }
            #pragma unroll
            for (int np = 0; np < 2; ++np) {
                uint32_t off = (uint32_t)(((bRow + np * 16) * SA + bCol + kk) * 2);
                uint32_t r0, r1, r2, r3;
                ldsm_x4(bBase + off, r0, r1, r2, r3);
                bH[np*2][0] = r0; bH[np*2][1] = r1; bH[np*2+1][0] = r2; bH[np*2+1][1] = r3;
                ldsm_x4(bBase + bLoff + off, r0, r1, r2, r3);
                bL[np*2][0] = r0; bL[np*2][1] = r1; bL[np*2+1][0] = r2; bL[np*2+1][1] = r3;
            }
            #pragma unroll
            for (int mt = 0; mt < 2; ++mt)
                #pragma unroll
                for (int nt = 0; nt < 4; ++nt) {
                    mma_bf16(acc[mt][nt], aH[mt], bH[nt]);   // hi*hi
                    mma_bf16(acc[mt][nt], aH[mt], bL[nt]);   // hi*lo
                    mma_bf16(acc[mt][nt], aL[mt], bH[nt]);   // lo*hi
                }
        }
        __syncthreads();
    }

    // ---- epilogue: fragment -> gmem, fused bias ----
    const int er = lane >> 2, ec = (lane & 3) * 2;
    #pragma unroll
    for (int mt = 0; mt < 2; ++mt) {
        #pragma unroll
        for (int nt = 0; nt < 4; ++nt) {
            const int n = n0 + wn * 32 + nt * 8 + ec;
            const float b0 = __ldg(bias + n), b1 = __ldg(bias + n + 1);
            const int mrow = m0 + wm * 32 + mt * 16 + er;
            float2 v;
            v.x = acc[mt][nt][0] + b0; v.y = acc[mt][nt][1] + b1;
            *(float2*)(out + (size_t)mrow * Ee + n) = v;
            v.x = acc[mt][nt][2] + b0; v.y = acc[mt][nt][3] + b1;
            *(float2*)(out + (size_t)(mrow + 8) * Ee + n) = v;
        }
    }
}

// patch_positions -> fp32 values (exact for 0..368), after tokens.
__global__ void write_positions(const int* __restrict__ ys,
                                const int* __restrict__ xs,
                                float* __restrict__ pos)
{
    int i = blockIdx.x * blockDim.x + threadIdx.x;
    if (i < Mm) {
        pos[2 * i + 0] = (float)ys[i];
        pos[2 * i + 1] = (float)xs[i];
    }
}

} // namespace

extern "C" void kernel_launch(void* const* d_in, const int* in_sizes, int n_in,
                              void* d_out, int out_size) {
    const float* x    = (const float*)d_in[0];
    const int*   ys   = (const int*)d_in[1];
    const int*   xs   = (const int*)d_in[2];
    const float* w    = (const float*)d_in[3];
    const float* bias = (const float*)d_in[4];
    float* out = (float*)d_out;

    dim3 grid(Ee / BN, Mm / BM);   // 6 x 288 = 1728 CTAs
    patch_embed_hmma<<<grid, THREADS>>>(x, ys, xs, w, bias, out);

    float* pos = out + (size_t)Mm * Ee;
    write_positions<<<(Mm + 255) / 256, 256>>>(ys, xs, pos);
}

// round 8
// speedup vs baseline: 2.3112x; 1.0791x over previous
#include <cuda_runtime.h>
#include <cuda_bf16.h>
#include <cstdint>

namespace {

constexpr int Bb = 64, Cc = 3, Hh = 384, Ww = 384, Pp = 16, Ee = 768;
constexpr int NP = (Hh / Pp) * (Ww / Pp);   // 576
constexpr int Mm = Bb * NP;                 // 36864
constexpr int Kk = Cc * Pp * Pp;            // 768

constexpr int BM = 128, BN = 128, BK = 32;  // CTA tile
constexpr int THREADS = 512;                // 16 warps: 4 (M) x 4 (N), 32x32 each
constexpr int SA = BK + 8;                  // smem row stride (bf16) -> 80B, LDSM conflict-free
constexpr int NITER = Kk / BK;              // 24

// dynamic smem: 2 stages x (AH, AL, BH, BL), each tile 128*SA bf16 = 10240 B
constexpr int TILE_B  = BM * SA * 2;        // 10240
constexpr int STAGE_B = 4 * TILE_B;         // 40960
constexpr int SMEM_B  = 2 * STAGE_B;        // 81920

// Pre-split weights (bf16 hi + residual lo), written by prep kernel each call.
__device__ __nv_bfloat16 g_whi[Ee * Kk];
__device__ __nv_bfloat16 g_wlo[Ee * Kk];

__device__ __forceinline__ uint32_t smem_u32(const void* p) {
    uint32_t a;
    asm("{ .reg .u64 t; cvta.to.shared.u64 t, %1; cvt.u32.u64 %0, t; }" : "=r"(a) : "l"(p));
    return a;
}

__device__ __forceinline__ void ldsm_x4(uint32_t addr, uint32_t& r0, uint32_t& r1,
                                        uint32_t& r2, uint32_t& r3) {
    asm volatile("ldmatrix.sync.aligned.m8n8.x4.shared.b16 {%0,%1,%2,%3}, [%4];"
                 : "=r"(r0), "=r"(r1), "=r"(r2), "=r"(r3) : "r"(addr));
}

__device__ __forceinline__ void mma_bf16(float* d, const uint32_t* a, const uint32_t* b) {
    asm volatile(
        "mma.sync.aligned.m16n8k16.row.col.f32.bf16.bf16.f32 "
        "{%0,%1,%2,%3}, {%4,%5,%6,%7}, {%8,%9}, {%0,%1,%2,%3};"
        : "+f"(d[0]), "+f"(d[1]), "+f"(d[2]), "+f"(d[3])
        : "r"(a[0]), "r"(a[1]), "r"(a[2]), "r"(a[3]), "r"(b[0]), "r"(b[1]));
}

// fp32 -> bf16 hi + bf16 lo residual (hi*hi + hi*lo + lo*hi ~ 16 mantissa bits).
__device__ __forceinline__ void split2(float v0, float v1, uint32_t& hi, uint32_t& lo) {
    __nv_bfloat16 h0 = __float2bfloat16(v0);
    __nv_bfloat16 h1 = __float2bfloat16(v1);
    __nv_bfloat16 l0 = __float2bfloat16(v0 - __bfloat162float(h0));
    __nv_bfloat16 l1 = __float2bfloat16(v1 - __bfloat162float(h1));
    hi = (uint32_t)__bfloat16_as_ushort(h0) | ((uint32_t)__bfloat16_as_ushort(h1) << 16);
    lo = (uint32_t)__bfloat16_as_ushort(l0) | ((uint32_t)__bfloat16_as_ushort(l1) << 16);
}

__global__ __launch_bounds__(256)
void prep_w(const float* __restrict__ w) {
    int i = (blockIdx.x * 256 + threadIdx.x) * 4;
    float4 v = *(const float4*)(w + i);
    uint32_t hi0, lo0, hi1, lo1;
    split2(v.x, v.y, hi0, lo0);
    split2(v.z, v.w, hi1, lo1);
    *(uint2*)&g_whi[i] = make_uint2(hi0, hi1);
    *(uint2*)&g_wlo[i] = make_uint2(lo0, lo1);
}

// Fused gather + split-bf16 HMMA GEMM, double-buffered smem, pre-split B.
__global__ __launch_bounds__(THREADS, 1)
void patch_embed_hmma(const float* __restrict__ x,
                      const int*   __restrict__ ys,
                      const int*   __restrict__ xs,
                      const float* __restrict__ bias,
                      float*       __restrict__ out)
{
    extern __shared__ char smem[];
    const uint32_t sbase = smem_u32(smem);

    const int tid = threadIdx.x;
    const int warpid = tid >> 5, lane = tid & 31;
    const int wm = warpid & 3, wn = warpid >> 2;     // warp coords in 4x4 grid
    const int m0 = blockIdx.y * BM, n0 = blockIdx.x * BN;

    // ---- loader mapping: 4 threads per row, 8 elems each ----
    const int lrow = tid >> 2;          // 0..127
    const int lseg = tid & 3;           // 8-elem chunk within the 32-K slice
    const int am = m0 + lrow;
    const int bimg = am / NP;
    const float* arow = x + ((size_t)(bimg * Cc) * Hh + ys[am]) * (size_t)Ww + xs[am];
    const __nv_bfloat16* bh_row = g_whi + (size_t)(n0 + lrow) * Kk + lseg * 8;
    const __nv_bfloat16* bl_row = g_wlo + (size_t)(n0 + lrow) * Kk + lseg * 8;

    float   af[8];
    uint4   bhv, blv;
    {   // prefetch kt = 0
        const int k0 = lseg * 8;
        const int c = k0 >> 8, r = (k0 >> 4) & 15, q = k0 & 15;
        const float* src = arow + ((size_t)c * Hh + r) * Ww + q;
        #pragma unroll
        for (int j = 0; j < 8; ++j) af[j] = __ldg(src + j);
        bhv = __ldg((const uint4*)bh_row);
        blv = __ldg((const uint4*)bl_row);
    }

    float acc[2][4][4];
    #pragma unroll
    for (int i = 0; i < 2; ++i)
        #pragma unroll
        for (int j = 0; j < 4; ++j)
            #pragma unroll
            for (int v = 0; v < 4; ++v) acc[i][j][v] = 0.f;

    // ldmatrix lane addressing (elements):
    const int g = lane >> 3, gi = lane & 7;
    const int aRow = wm * 32 + (g & 1) * 8 + gi;   // + mt*16
    const int aCol = (g >> 1) * 8;                 // + ks*16
    const int bRow = wn * 32 + (g >> 1) * 8 + gi;  // + np*16
    const int bCol = (g & 1) * 8;                  // + ks*16

    const uint32_t sts_off = (uint32_t)((lrow * SA + lseg * 8) * 2);

    // initial STS into stage 0
    {
        uint32_t hi[4], lo[4];
        #pragma unroll
        for (int j = 0; j < 4; ++j) split2(af[2*j], af[2*j+1], hi[j], lo[j]);
        char* st = smem;  // stage 0
        *(uint4*)(st + 0 * TILE_B + sts_off) = make_uint4(hi[0], hi[1], hi[2], hi[3]);
        *(uint4*)(st + 1 * TILE_B + sts_off) = make_uint4(lo[0], lo[1], lo[2], lo[3]);
        *(uint4*)(st + 2 * TILE_B + sts_off) = bhv;
        *(uint4*)(st + 3 * TILE_B + sts_off) = blv;
    }
    __syncthreads();

    #pragma unroll 1
    for (int kt = 0; kt < NITER; ++kt) {
        // prefetch next k-slice into regs (hidden under mma phase)
        if (kt + 1 < NITER) {
            const int k0 = (kt + 1) * BK + lseg * 8;
            const int c = k0 >> 8, r = (k0 >> 4) & 15, q = k0 & 15;
            const float* src = arow + ((size_t)c * Hh + r) * Ww + q;
            #pragma unroll
            for (int j = 0; j < 8; ++j) af[j] = __ldg(src + j);
            bhv = __ldg((const uint4*)(bh_row + (kt + 1) * BK));
            blv = __ldg((const uint4*)(bl_row + (kt + 1) * BK));
        }

        // ---- mma on stage kt&1 ----
        const uint32_t stg = sbase + (uint32_t)((kt & 1) * STAGE_B);
        #pragma unroll
        for (int ks = 0; ks < 2; ++ks) {
            const int kk = ks * 16;
            uint32_t aH[2][4], aL[2][4], bH[4][2], bL[4][2];
            #pragma unroll
            for (int mt = 0; mt < 2; ++mt) {
                uint32_t off = (uint32_t)(((aRow + mt * 16) * SA + aCol + kk) * 2);
                ldsm_x4(stg + 0 * TILE_B + off, aH[mt][0], aH[mt][1], aH[mt][2], aH[mt][3]);
                ldsm_x4(stg + 1 * TILE_B + off, aL[mt][0], aL[mt][1], aL[mt][2], aL[mt][3]);
            }
            #pragma unroll
            for (int np = 0; np < 2; ++np) {
                uint32_t off = (uint32_t)(((bRow + np * 16) * SA + bCol + kk) * 2);
                uint32_t r0, r1, r2, r3;
                ldsm_x4(stg + 2 * TILE_B + off, r0, r1, r2, r3);
                bH[np*2][0] = r0; bH[np*2][1] = r1; bH[np*2+1][0] = r2; bH[np*2+1][1] = r3;
                ldsm_x4(stg + 3 * TILE_B + off, r0, r1, r2, r3);
                bL[np*2][0] = r0; bL[np*2][1] = r1; bL[np*2+1][0] = r2; bL[np*2+1][1] = r3;
            }
            #pragma unroll
            for (int mt = 0; mt < 2; ++mt)
                #pragma unroll
                for (int nt = 0; nt < 4; ++nt) {
                    mma_bf16(acc[mt][nt], aH[mt], bH[nt]);   // hi*hi
                    mma_bf16(acc[mt][nt], aH[mt], bL[nt]);   // hi*lo
                    mma_bf16(acc[mt][nt], aL[mt], bH[nt]);   // lo*hi
                }
        }

        // ---- STS next slice into the other stage ----
        if (kt + 1 < NITER) {
            uint32_t hi[4], lo[4];
            #pragma unroll
            for (int j = 0; j < 4; ++j) split2(af[2*j], af[2*j+1], hi[j], lo[j]);
            char* st = smem + ((kt + 1) & 1) * STAGE_B;
            *(uint4*)(st + 0 * TILE_B + sts_off) = make_uint4(hi[0], hi[1], hi[2], hi[3]);
            *(uint4*)(st + 1 * TILE_B + sts_off) = make_uint4(lo[0], lo[1], lo[2], lo[3]);
            *(uint4*)(st + 2 * TILE_B + sts_off) = bhv;
            *(uint4*)(st + 3 * TILE_B + sts_off) = blv;
        }
        __syncthreads();
    }

    // ---- epilogue: fragment -> gmem, fused bias ----
    const int er = lane >> 2, ec = (lane & 3) * 2;
    #pragma unroll
    for (int mt = 0; mt < 2; ++mt) {
        #pragma unroll
        for (int nt = 0; nt < 4; ++nt) {
            const int n = n0 + wn * 32 + nt * 8 + ec;
            const float b0 = __ldg(bias + n), b1 = __ldg(bias + n + 1);
            const int mrow = m0 + wm * 32 + mt * 16 + er;
            float2 v;
            v.x = acc[mt][nt][0] + b0; v.y = acc[mt][nt][1] + b1;
            *(float2*)(out + (size_t)mrow * Ee + n) = v;
            v.x = acc[mt][nt][2] + b0; v.y = acc[mt][nt][3] + b1;
            *(float2*)(out + (size_t)(mrow + 8) * Ee + n) = v;
        }
    }
}

// patch_positions -> fp32 values (exact for 0..368), after tokens.
__global__ void write_positions(const int* __restrict__ ys,
                                const int* __restrict__ xs,
                                float* __restrict__ pos)
{
    int i = blockIdx.x * blockDim.x + threadIdx.x;
    if (i < Mm) {
        pos[2 * i + 0] = (float)ys[i];
        pos[2 * i + 1] = (float)xs[i];
    }
}

} // namespace

extern "C" void kernel_launch(void* const* d_in, const int* in_sizes, int n_in,
                              void* d_out, int out_size) {
    const float* x    = (const float*)d_in[0];
    const int*   ys   = (const int*)d_in[1];
    const int*   xs   = (const int*)d_in[2];
    const float* w    = (const float*)d_in[3];
    const float* bias = (const float*)d_in[4];
    float* out = (float*)d_out;

    static int smem_set = 0;
    if (!smem_set) {
        cudaFuncSetAttribute(patch_embed_hmma,
                             cudaFuncAttributeMaxDynamicSharedMemorySize, SMEM_B);
        smem_set = 1;
    }

    // Order matters for ncu (-s 5 -c 1 lands on launch #6 == last of 2nd call):
    // keep the GEMM last so the profiler captures it.
    prep_w<<<Ee * Kk / (256 * 4), 256>>>(w);

    float* pos = out + (size_t)Mm * Ee;
    write_positions<<<(Mm + 255) / 256, 256>>>(ys, xs, pos);

    dim3 grid(Ee / BN, Mm / BM);   // 6 x 288 = 1728 CTAs
    patch_embed_hmma<<<grid, THREADS, SMEM_B>>>(x, ys, xs, bias, out);
}

// round 9
// speedup vs baseline: 2.8937x; 1.2520x over previous
#include <cuda_runtime.h>
#include <cuda_bf16.h>
#include <cstdint>

namespace {

constexpr int Bb = 64, Cc = 3, Hh = 384, Ww = 384, Pp = 16, Ee = 768;
constexpr int NP = (Hh / Pp) * (Ww / Pp);   // 576
constexpr int Mm = Bb * NP;                 // 36864
constexpr int Kk = Cc * Pp * Pp;            // 768

constexpr int BM = 128, BN = 128, BK = 32;  // CTA tile
constexpr int THREADS = 512;                // 16 warps: 4(M) x 4(N), 32x32 tiles
constexpr int SA = 40;                      // smem row stride in bf16 (80B) - LDSM conflict-free
constexpr int NITER = Kk / BK;              // 24

constexpr int TILE_B  = BM * SA * 2;        // 10240 B per tile
constexpr int STAGE_B = 4 * TILE_B;         // AH, AL, BH, BL
constexpr int SMEM_B  = 2 * STAGE_B;        // 81920

// Pre-split operands (bf16 hi + residual lo), rebuilt every call.
__device__ __nv_bfloat16 g_whi[Ee * Kk];
__device__ __nv_bfloat16 g_wlo[Ee * Kk];
__device__ __nv_bfloat16 g_ahi[(size_t)Mm * Kk];
__device__ __nv_bfloat16 g_alo[(size_t)Mm * Kk];

__device__ __forceinline__ uint32_t smem_u32(const void* p) {
    uint32_t a;
    asm("{ .reg .u64 t; cvta.to.shared.u64 t, %1; cvt.u32.u64 %0, t; }" : "=r"(a) : "l"(p));
    return a;
}
__device__ __forceinline__ void ldsm_x4(uint32_t addr, uint32_t& r0, uint32_t& r1,
                                        uint32_t& r2, uint32_t& r3) {
    asm volatile("ldmatrix.sync.aligned.m8n8.x4.shared.b16 {%0,%1,%2,%3}, [%4];"
                 : "=r"(r0), "=r"(r1), "=r"(r2), "=r"(r3) : "r"(addr));
}
__device__ __forceinline__ void mma_bf16(float* d, const uint32_t* a, const uint32_t* b) {
    asm volatile(
        "mma.sync.aligned.m16n8k16.row.col.f32.bf16.bf16.f32 "
        "{%0,%1,%2,%3}, {%4,%5,%6,%7}, {%8,%9}, {%0,%1,%2,%3};"
        : "+f"(d[0]), "+f"(d[1]), "+f"(d[2]), "+f"(d[3])
        : "r"(a[0]), "r"(a[1]), "r"(a[2]), "r"(a[3]), "r"(b[0]), "r"(b[1]));
}
__device__ __forceinline__ void cp16(uint32_t dst, const void* src) {
    asm volatile("cp.async.ca.shared.global [%0], [%1], 16;" :: "r"(dst), "l"(src));
}
__device__ __forceinline__ void cp_commit() {
    asm volatile("cp.async.commit_group;" ::: "memory");
}
__device__ __forceinline__ void cp_wait0() {
    asm volatile("cp.async.wait_group 0;" ::: "memory");
}

// fp32 -> bf16 hi + bf16 lo residual (3-product scheme ~ 16 mantissa bits).
__device__ __forceinline__ void split2(float v0, float v1, uint32_t& hi, uint32_t& lo) {
    __nv_bfloat16 h0 = __float2bfloat16(v0);
    __nv_bfloat16 h1 = __float2bfloat16(v1);
    __nv_bfloat16 l0 = __float2bfloat16(v0 - __bfloat162float(h0));
    __nv_bfloat16 l1 = __float2bfloat16(v1 - __bfloat162float(h1));
    hi = (uint32_t)__bfloat16_as_ushort(h0) | ((uint32_t)__bfloat16_as_ushort(h1) << 16);
    lo = (uint32_t)__bfloat16_as_ushort(l0) | ((uint32_t)__bfloat16_as_ushort(l1) << 16);
}

__global__ __launch_bounds__(256)
void prep_w(const float* __restrict__ w) {
    int i = (blockIdx.x * 256 + threadIdx.x) * 4;
    float4 v = *(const float4*)(w + i);
    uint32_t hi0, lo0, hi1, lo1;
    split2(v.x, v.y, hi0, lo0);
    split2(v.z, v.w, hi1, lo1);
    *(uint2*)&g_whi[i] = make_uint2(hi0, hi1);
    *(uint2*)&g_wlo[i] = make_uint2(lo0, lo1);
}

// Gather all patches once, split to bf16 hi/lo, write K-major [M, 768].
// One thread per 8-element k-group (contiguous image span). Also emits the
// fp32 patch_positions (exact for 0..368).
__global__ __launch_bounds__(256)
void prep_x(const float* __restrict__ x,
            const int* __restrict__ ys, const int* __restrict__ xs,
            float* __restrict__ pos) {
    int t = blockIdx.x * 256 + threadIdx.x;      // t < Mm * 96
    int m = t / 96, g = t - m * 96;
    int y0 = ys[m], x0 = xs[m];
    if (g == 0) {
        pos[2 * m + 0] = (float)y0;
        pos[2 * m + 1] = (float)x0;
    }
    int k0 = g * 8;
    int c = k0 >> 8, r = (k0 >> 4) & 15, q = k0 & 15;
    int bimg = m / NP;
    const float* src = x + ((size_t)(bimg * Cc + c) * Hh + y0 + r) * Ww + x0 + q;
    float v[8];
    #pragma unroll
    for (int j = 0; j < 8; ++j) v[j] = __ldg(src + j);
    uint32_t hi[4], lo[4];
    #pragma unroll
    for (int j = 0; j < 4; ++j) split2(v[2 * j], v[2 * j + 1], hi[j], lo[j]);
    size_t o = (size_t)m * Kk + k0;
    *(uint4*)&g_ahi[o] = make_uint4(hi[0], hi[1], hi[2], hi[3]);
    *(uint4*)&g_alo[o] = make_uint4(lo[0], lo[1], lo[2], lo[3]);
}

// Pure bf16 split-GEMM: cp.async double-buffered, LDSM + HMMA only in loop.
__global__ __launch_bounds__(THREADS, 1)
void patch_embed_hmma(const float* __restrict__ bias, float* __restrict__ out)
{
    extern __shared__ char smem[];
    const uint32_t sbase = smem_u32(smem);

    const int tid = threadIdx.x;
    const int warpid = tid >> 5, lane = tid & 31;
    const int wm = warpid & 3, wn = warpid >> 2;
    const int m0 = blockIdx.y * BM, n0 = blockIdx.x * BN;

    // cp.async mapping: 512 threads = 128 rows x 4 chunks of 16B per tile.
    const int row = tid >> 2, c4 = tid & 3;
    const __nv_bfloat16* asrcH = g_ahi + (size_t)(m0 + row) * Kk + c4 * 8;
    const __nv_bfloat16* asrcL = g_alo + (size_t)(m0 + row) * Kk + c4 * 8;
    const __nv_bfloat16* bsrcH = g_whi + (size_t)(n0 + row) * Kk + c4 * 8;
    const __nv_bfloat16* bsrcL = g_wlo + (size_t)(n0 + row) * Kk + c4 * 8;
    const uint32_t dst_off = (uint32_t)(row * (SA * 2) + c4 * 16);

    float acc[2][4][4];
    #pragma unroll
    for (int i = 0; i < 2; ++i)
        #pragma unroll
        for (int j = 0; j < 4; ++j)
            #pragma unroll
            for (int v = 0; v < 4; ++v) acc[i][j][v] = 0.f;

    // ldmatrix lane addressing (elements)
    const int g = lane >> 3, gi = lane & 7;
    const int aRow = wm * 32 + (g & 1) * 8 + gi;   // + mt*16
    const int aCol = (g >> 1) * 8;                 // + ks*16
    const int bRow = wn * 32 + (g >> 1) * 8 + gi;  // + np*16
    const int bCol = (g & 1) * 8;                  // + ks*16

    // preload stage 0
    {
        uint32_t d = sbase + dst_off;
        cp16(d + 0 * TILE_B, asrcH);
        cp16(d + 1 * TILE_B, asrcL);
        cp16(d + 2 * TILE_B, bsrcH);
        cp16(d + 3 * TILE_B, bsrcL);
        cp_commit();
        cp_wait0();
    }
    __syncthreads();

    #pragma unroll 1
    for (int kt = 0; kt < NITER; ++kt) {
        if (kt + 1 < NITER) {
            uint32_t d = sbase + ((kt + 1) & 1) * STAGE_B + dst_off;
            int ko = (kt + 1) * BK;
            cp16(d + 0 * TILE_B, asrcH + ko);
            cp16(d + 1 * TILE_B, asrcL + ko);
            cp16(d + 2 * TILE_B, bsrcH + ko);
            cp16(d + 3 * TILE_B, bsrcL + ko);
            cp_commit();
        }

        const uint32_t stg = sbase + (uint32_t)((kt & 1) * STAGE_B);
        #pragma unroll
        for (int ks = 0; ks < 2; ++ks) {
            const int kk = ks * 16;
            uint32_t aH[2][4], aL[2][4], bH[4][2], bL[4][2];
            #pragma unroll
            for (int mt = 0; mt < 2; ++mt) {
                uint32_t off = (uint32_t)(((aRow + mt * 16) * SA + aCol + kk) * 2);
                ldsm_x4(stg + 0 * TILE_B + off, aH[mt][0], aH[mt][1], aH[mt][2], aH[mt][3]);
                ldsm_x4(stg + 1 * TILE_B + off, aL[mt][0], aL[mt][1], aL[mt][2], aL[mt][3]);
            }
            #pragma unroll
            for (int np = 0; np < 2; ++np) {
                uint32_t off = (uint32_t)(((bRow + np * 16) * SA + bCol + kk) * 2);
                uint32_t r0, r1, r2, r3;
                ldsm_x4(stg + 2 * TILE_B + off, r0, r1, r2, r3);
                bH[np*2][0] = r0; bH[np*2][1] = r1; bH[np*2+1][0] = r2; bH[np*2+1][1] = r3;
                ldsm_x4(stg + 3 * TILE_B + off, r0, r1, r2, r3);
                bL[np*2][0] = r0; bL[np*2][1] = r1; bL[np*2+1][0] = r2; bL[np*2+1][1] = r3;
            }
            #pragma unroll
            for (int mt = 0; mt < 2; ++mt)
                #pragma unroll
                for (int nt = 0; nt < 4; ++nt) {
                    mma_bf16(acc[mt][nt], aH[mt], bH[nt]);   // hi*hi
                    mma_bf16(acc[mt][nt], aH[mt], bL[nt]);   // hi*lo
                    mma_bf16(acc[mt][nt], aL[mt], bH[nt]);   // lo*hi
                }
        }

        if (kt + 1 < NITER) cp_wait0();
        __syncthreads();
    }

    // epilogue: fragments -> gmem, fused bias
    const int er = lane >> 2, ec = (lane & 3) * 2;
    #pragma unroll
    for (int mt = 0; mt < 2; ++mt) {
        #pragma unroll
        for (int nt = 0; nt < 4; ++nt) {
            const int n = n0 + wn * 32 + nt * 8 + ec;
            const float b0 = __ldg(bias + n), b1 = __ldg(bias + n + 1);
            const int mrow = m0 + wm * 32 + mt * 16 + er;
            float2 v;
            v.x = acc[mt][nt][0] + b0; v.y = acc[mt][nt][1] + b1;
            *(float2*)(out + (size_t)mrow * Ee + n) = v;
            v.x = acc[mt][nt][2] + b0; v.y = acc[mt][nt][3] + b1;
            *(float2*)(out + (size_t)(mrow + 8) * Ee + n) = v;
        }
    }
}

} // namespace

extern "C" void kernel_launch(void* const* d_in, const int* in_sizes, int n_in,
                              void* d_out, int out_size) {
    const float* x    = (const float*)d_in[0];
    const int*   ys   = (const int*)d_in[1];
    const int*   xs   = (const int*)d_in[2];
    const float* w    = (const float*)d_in[3];
    const float* bias = (const float*)d_in[4];
    float* out = (float*)d_out;

    static int smem_set = 0;
    if (!smem_set) {
        cudaFuncSetAttribute(patch_embed_hmma,
                             cudaFuncAttributeMaxDynamicSharedMemorySize, SMEM_B);
        smem_set = 1;
    }

    prep_w<<<Ee * Kk / (256 * 4), 256>>>(w);

    float* pos = out + (size_t)Mm * Ee;
    prep_x<<<Mm * 96 / 256, 256>>>(x, ys, xs, pos);

    dim3 grid(Ee / BN, Mm / BM);   // 6 x 288 = 1728 CTAs
    patch_embed_hmma<<<grid, THREADS, SMEM_B>>>(bias, out);
}

// round 10
// speedup vs baseline: 3.6554x; 1.2632x over previous
#include <cuda_runtime.h>
#include <cuda_fp16.h>
#include <cstdint>

namespace {

constexpr int Bb = 64, Cc = 3, Hh = 384, Ww = 384, Pp = 16, Ee = 768;
constexpr int NP = (Hh / Pp) * (Ww / Pp);   // 576
constexpr int Mm = Bb * NP;                 // 36864
constexpr int Kk = Cc * Pp * Pp;            // 768

constexpr int BM = 128, BN = 128, BK = 32;  // CTA tile
constexpr int THREADS = 512;                // 16 warps: 4(M) x 4(N), 32x32 tiles
constexpr int SA = 40;                      // smem row stride fp16 (80B) - LDSM conflict-free
constexpr int NITER = Kk / BK;              // 24

constexpr int TILE_B  = BM * SA * 2;        // 10240 B per tile
constexpr int STAGE_B = 3 * TILE_B;         // AH, AL, BH (no B-lo)
constexpr int SMEM_B  = 2 * STAGE_B;        // 61440

// Pre-split operands, rebuilt every call. A: fp16 hi + residual lo. B: fp16.
__device__ __half g_wh[Ee * Kk];
__device__ __half g_ahi[(size_t)Mm * Kk];
__device__ __half g_alo[(size_t)Mm * Kk];

__device__ __forceinline__ uint32_t smem_u32(const void* p) {
    uint32_t a;
    asm("{ .reg .u64 t; cvta.to.shared.u64 t, %1; cvt.u32.u64 %0, t; }" : "=r"(a) : "l"(p));
    return a;
}
__device__ __forceinline__ void ldsm_x4(uint32_t addr, uint32_t& r0, uint32_t& r1,
                                        uint32_t& r2, uint32_t& r3) {
    asm volatile("ldmatrix.sync.aligned.m8n8.x4.shared.b16 {%0,%1,%2,%3}, [%4];"
                 : "=r"(r0), "=r"(r1), "=r"(r2), "=r"(r3) : "r"(addr));
}
__device__ __forceinline__ void mma_f16(float* d, const uint32_t* a, const uint32_t* b) {
    asm volatile(
        "mma.sync.aligned.m16n8k16.row.col.f32.f16.f16.f32 "
        "{%0,%1,%2,%3}, {%4,%5,%6,%7}, {%8,%9}, {%0,%1,%2,%3};"
        : "+f"(d[0]), "+f"(d[1]), "+f"(d[2]), "+f"(d[3])
        : "r"(a[0]), "r"(a[1]), "r"(a[2]), "r"(a[3]), "r"(b[0]), "r"(b[1]));
}
__device__ __forceinline__ void cp16(uint32_t dst, const void* src) {
    asm volatile("cp.async.ca.shared.global [%0], [%1], 16;" :: "r"(dst), "l"(src));
}
__device__ __forceinline__ void cp_commit() {
    asm volatile("cp.async.commit_group;" ::: "memory");
}
__device__ __forceinline__ void cp_wait0() {
    asm volatile("cp.async.wait_group 0;" ::: "memory");
}

// fp32 -> fp16 hi + fp16 lo residual. (hi+lo) carries ~22 mantissa bits.
__device__ __forceinline__ void split2h(float v0, float v1, uint32_t& hi, uint32_t& lo) {
    __half h0 = __float2half_rn(v0);
    __half h1 = __float2half_rn(v1);
    __half l0 = __float2half_rn(v0 - __half2float(h0));
    __half l1 = __float2half_rn(v1 - __half2float(h1));
    hi = (uint32_t)__half_as_ushort(h0) | ((uint32_t)__half_as_ushort(h1) << 16);
    lo = (uint32_t)__half_as_ushort(l0) | ((uint32_t)__half_as_ushort(l1) << 16);
}

__global__ __launch_bounds__(256)
void prep_w(const float* __restrict__ w) {
    int i = (blockIdx.x * 256 + threadIdx.x) * 4;
    float4 v = *(const float4*)(w + i);
    __half2 a = __floats2half2_rn(v.x, v.y);
    __half2 b = __floats2half2_rn(v.z, v.w);
    *(uint2*)&g_wh[i] = make_uint2(*(uint32_t*)&a, *(uint32_t*)&b);
}

// Gather all patches once, split to fp16 hi/lo, write K-major [M, 768].
// One thread per 8-element k-group (contiguous image span). Also emits the
// fp32 patch_positions (exact for 0..368).
__global__ __launch_bounds__(256)
void prep_x(const float* __restrict__ x,
            const int* __restrict__ ys, const int* __restrict__ xs,
            float* __restrict__ pos) {
    int t = blockIdx.x * 256 + threadIdx.x;      // t < Mm * 96
    int m = t / 96, g = t - m * 96;
    int y0 = ys[m], x0 = xs[m];
    if (g == 0) {
        pos[2 * m + 0] = (float)y0;
        pos[2 * m + 1] = (float)x0;
    }
    int k0 = g * 8;
    int c = k0 >> 8, r = (k0 >> 4) & 15, q = k0 & 15;
    int bimg = m / NP;
    const float* src = x + ((size_t)(bimg * Cc + c) * Hh + y0 + r) * Ww + x0 + q;
    float v[8];
    #pragma unroll
    for (int j = 0; j < 8; ++j) v[j] = __ldg(src + j);
    uint32_t hi[4], lo[4];
    #pragma unroll
    for (int j = 0; j < 4; ++j) split2h(v[2 * j], v[2 * j + 1], hi[j], lo[j]);
    size_t o = (size_t)m * Kk + k0;
    *(uint4*)&g_ahi[o] = make_uint4(hi[0], hi[1], hi[2], hi[3]);
    *(uint4*)&g_alo[o] = make_uint4(lo[0], lo[1], lo[2], lo[3]);
}

// fp16 split GEMM: tokens = (Ahi + Alo) * Wh^T + bias.
// 2 HMMA products per tile-step (error = a * w_lo_dropped ~= 2^-11 rel).
__global__ __launch_bounds__(THREADS, 1)
void patch_embed_hmma(const float* __restrict__ bias, float* __restrict__ out)
{
    extern __shared__ char smem[];
    const uint32_t sbase = smem_u32(smem);

    const int tid = threadIdx.x;
    const int warpid = tid >> 5, lane = tid & 31;
    const int wm = warpid & 3, wn = warpid >> 2;
    const int m0 = blockIdx.y * BM, n0 = blockIdx.x * BN;

    // cp.async mapping: 512 threads = 128 rows x 4 chunks of 16B per tile.
    const int row = tid >> 2, c4 = tid & 3;
    const __half* asrcH = g_ahi + (size_t)(m0 + row) * Kk + c4 * 8;
    const __half* asrcL = g_alo + (size_t)(m0 + row) * Kk + c4 * 8;
    const __half* bsrcH = g_wh  + (size_t)(n0 + row) * Kk + c4 * 8;
    const uint32_t dst_off = (uint32_t)(row * (SA * 2) + c4 * 16);

    float acc[2][4][4];
    #pragma unroll
    for (int i = 0; i < 2; ++i)
        #pragma unroll
        for (int j = 0; j < 4; ++j)
            #pragma unroll
            for (int v = 0; v < 4; ++v) acc[i][j][v] = 0.f;

    // ldmatrix lane addressing (elements)
    const int g = lane >> 3, gi = lane & 7;
    const int aRow = wm * 32 + (g & 1) * 8 + gi;   // + mt*16
    const int aCol = (g >> 1) * 8;                 // + ks*16
    const int bRow = wn * 32 + (g >> 1) * 8 + gi;  // + np*16
    const int bCol = (g & 1) * 8;                  // + ks*16

    // preload stage 0
    {
        uint32_t d = sbase + dst_off;
        cp16(d + 0 * TILE_B, asrcH);
        cp16(d + 1 * TILE_B, asrcL);
        cp16(d + 2 * TILE_B, bsrcH);
        cp_commit();
        cp_wait0();
    }
    __syncthreads();

    #pragma unroll 1
    for (int kt = 0; kt < NITER; ++kt) {
        if (kt + 1 < NITER) {
            uint32_t d = sbase + ((kt + 1) & 1) * STAGE_B + dst_off;
            int ko = (kt + 1) * BK;
            cp16(d + 0 * TILE_B, asrcH + ko);
            cp16(d + 1 * TILE_B, asrcL + ko);
            cp16(d + 2 * TILE_B, bsrcH + ko);
            cp_commit();
        }

        const uint32_t stg = sbase + (uint32_t)((kt & 1) * STAGE_B);
        #pragma unroll
        for (int ks = 0; ks < 2; ++ks) {
            const int kk = ks * 16;
            uint32_t aH[2][4], aL[2][4], bH[4][2];
            #pragma unroll
            for (int mt = 0; mt < 2; ++mt) {
                uint32_t off = (uint32_t)(((aRow + mt * 16) * SA + aCol + kk) * 2);
                ldsm_x4(stg + 0 * TILE_B + off, aH[mt][0], aH[mt][1], aH[mt][2], aH[mt][3]);
                ldsm_x4(stg + 1 * TILE_B + off, aL[mt][0], aL[mt][1], aL[mt][2], aL[mt][3]);
            }
            #pragma unroll
            for (int np = 0; np < 2; ++np) {
                uint32_t off = (uint32_t)(((bRow + np * 16) * SA + bCol + kk) * 2);
                uint32_t r0, r1, r2, r3;
                ldsm_x4(stg + 2 * TILE_B + off, r0, r1, r2, r3);
                bH[np*2][0] = r0; bH[np*2][1] = r1; bH[np*2+1][0] = r2; bH[np*2+1][1] = r3;
            }
            #pragma unroll
            for (int mt = 0; mt < 2; ++mt)
                #pragma unroll
                for (int nt = 0; nt < 4; ++nt) {
                    mma_f16(acc[mt][nt], aH[mt], bH[nt]);   // hiA * B
                    mma_f16(acc[mt][nt], aL[mt], bH[nt]);   // loA * B
                }
        }

        if (kt + 1 < NITER) cp_wait0();
        __syncthreads();
    }

    // epilogue: fragments -> gmem, fused bias
    const int er = lane >> 2, ec = (lane & 3) * 2;
    #pragma unroll
    for (int mt = 0; mt < 2; ++mt) {
        #pragma unroll
        for (int nt = 0; nt < 4; ++nt) {
            const int n = n0 + wn * 32 + nt * 8 + ec;
            const float b0 = __ldg(bias + n), b1 = __ldg(bias + n + 1);
            const int mrow = m0 + wm * 32 + mt * 16 + er;
            float2 v;
            v.x = acc[mt][nt][0] + b0; v.y = acc[mt][nt][1] + b1;
            *(float2*)(out + (size_t)mrow * Ee + n) = v;
            v.x = acc[mt][nt][2] + b0; v.y = acc[mt][nt][3] + b1;
            *(float2*)(out + (size_t)(mrow + 8) * Ee + n) = v;
        }
    }
}

} // namespace

extern "C" void kernel_launch(void* const* d_in, const int* in_sizes, int n_in,
                              void* d_out, int out_size) {
    const float* x    = (const float*)d_in[0];
    const int*   ys   = (const int*)d_in[1];
    const int*   xs   = (const int*)d_in[2];
    const float* w    = (const float*)d_in[3];
    const float* bias = (const float*)d_in[4];
    float* out = (float*)d_out;

    static int smem_set = 0;
    if (!smem_set) {
        cudaFuncSetAttribute(patch_embed_hmma,
                             cudaFuncAttributeMaxDynamicSharedMemorySize, SMEM_B);
        smem_set = 1;
    }

    prep_w<<<Ee * Kk / (256 * 4), 256>>>(w);

    float* pos = out + (size_t)Mm * Ee;
    prep_x<<<Mm * 96 / 256, 256>>>(x, ys, xs, pos);

    dim3 grid(Ee / BN, Mm / BM);   // 6 x 288 = 1728 CTAs
    patch_embed_hmma<<<grid, THREADS, SMEM_B>>>(bias, out);
}